// round 1
// baseline (speedup 1.0000x reference)
#include <cuda_runtime.h>
#include <math.h>

#define BATCH   64
#define CH      96
#define HW      12544
#define MTOK    6
#define HEADS   4
#define RQ      24        // HEADS * MTOK query rows per batch
#define DMODEL  192
#define QDIM    384       // HEADS * CH
#define SCALE_F 0.10206207261596575f  // 96^-0.5
#define SPLITS  7
#define CHUNK   1792      // HW / SPLITS
#define TILE    128
#define TILES_PER 14      // CHUNK / TILE
#define XSTRIDE 132       // 128 + 4 pad: float4-aligned, conflict-free both ways

// scratch (device globals: no allocation allowed)
__device__ float g_Q [BATCH * RQ * CH];
__device__ float g_Mx[BATCH * SPLITS * RQ];
__device__ float g_Lx[BATCH * SPLITS * RQ];
__device__ float g_Ox[BATCH * SPLITS * RQ * CH];

// ---------------------------------------------------------------------------
// Kernel 1: Q projection. q[b, h*6+m, c] = SCALE * (z[b,m,:] @ Wq[:, h*96+c] + bq)
// ---------------------------------------------------------------------------
__global__ __launch_bounds__(256) void qproj_kernel(
    const float* __restrict__ z, const float* __restrict__ Wq,
    const float* __restrict__ bq)
{
    __shared__ float sz[MTOK * DMODEL];
    const int b = blockIdx.x, tid = threadIdx.x;
    for (int i = tid; i < MTOK * DMODEL; i += 256)
        sz[i] = z[b * MTOK * DMODEL + i];
    __syncthreads();

    for (int o = tid; o < RQ * CH; o += 256) {
        const int r = o / CH, c = o - r * CH;
        const int h = r / MTOK, m = r - h * MTOK;
        const int col = h * CH + c;
        float a = bq[col];
        const float* zr = &sz[m * DMODEL];
        #pragma unroll 8
        for (int k = 0; k < DMODEL; ++k)
            a = fmaf(zr[k], Wq[k * QDIM + col], a);
        g_Q[(b * RQ + r) * CH + c] = a * SCALE_F;
    }
}

// ---------------------------------------------------------------------------
// Kernel 2: flash attention partials over split-KV.
// grid (SPLITS, BATCH), 256 threads. Warp w owns query rows 3w..3w+2.
// Per thread: output accumulators for 3 q-rows x 3 channels (c = lane + 32*i).
// ---------------------------------------------------------------------------
__global__ __launch_bounds__(256) void attn_partial_kernel(const float* __restrict__ x)
{
    extern __shared__ float smem[];
    float* sQ = smem;                    // RQ*CH      = 2304
    float* sX = sQ + RQ * CH;            // CH*XSTRIDE = 12672
    float* sP = sX + CH * XSTRIDE;       // RQ*TILE    = 3072
    float* sM = sP + RQ * TILE;          // RQ
    float* sL = sM + RQ;                 // RQ
    float* sA = sL + RQ;                 // RQ

    const int b = blockIdx.y, s = blockIdx.x;
    const int tid = threadIdx.x, lane = tid & 31, warp = tid >> 5;
    const int q0 = 3 * warp;

    for (int i = tid; i < RQ * CH; i += 256) sQ[i] = g_Q[b * RQ * CH + i];
    if (tid < RQ) { sM[tid] = -1e30f; sL[tid] = 0.f; }

    float acc[3][3];
    #pragma unroll
    for (int j = 0; j < 3; ++j)
        #pragma unroll
        for (int i = 0; i < 3; ++i) acc[j][i] = 0.f;

    const float* xb = x + (size_t)b * CH * HW + (size_t)s * CHUNK;

    for (int t = 0; t < TILES_PER; ++t) {
        __syncthreads();   // protects sX/sP reuse and initial sQ/sM fill

        // ---- load X tile [CH][TILE] fp32, float4 coalesced ----
        {
            const float* xt = xb + t * TILE;
            for (int i = tid; i < CH * (TILE / 4); i += 256) {
                const int c  = i >> 5;           // TILE/4 = 32
                const int n4 = (i & 31) << 2;
                float4 v = *reinterpret_cast<const float4*>(xt + (size_t)c * HW + n4);
                *reinterpret_cast<float4*>(&sX[c * XSTRIDE + n4]) = v;
            }
        }
        __syncthreads();

        // ---- scores: rows q0..q0+2, lane covers n = 4*lane .. 4*lane+3 ----
        float sc[3][4];
        #pragma unroll
        for (int j = 0; j < 3; ++j)
            #pragma unroll
            for (int jj = 0; jj < 4; ++jj) sc[j][jj] = 0.f;

        #pragma unroll 2
        for (int c4 = 0; c4 < CH; c4 += 4) {
            float4 qv[3];
            #pragma unroll
            for (int j = 0; j < 3; ++j)
                qv[j] = *reinterpret_cast<const float4*>(&sQ[(q0 + j) * CH + c4]);
            #pragma unroll
            for (int cc = 0; cc < 4; ++cc) {
                const float4 xv = *reinterpret_cast<const float4*>(
                    &sX[(c4 + cc) * XSTRIDE + 4 * lane]);
                #pragma unroll
                for (int j = 0; j < 3; ++j) {
                    const float qf = reinterpret_cast<const float*>(&qv[j])[cc];
                    sc[j][0] = fmaf(qf, xv.x, sc[j][0]);
                    sc[j][1] = fmaf(qf, xv.y, sc[j][1]);
                    sc[j][2] = fmaf(qf, xv.z, sc[j][2]);
                    sc[j][3] = fmaf(qf, xv.w, sc[j][3]);
                }
            }
        }

        // ---- online softmax update (warp-local: full row lives in this warp) ----
        #pragma unroll
        for (int j = 0; j < 3; ++j) {
            const int q = q0 + j;
            float mx = fmaxf(fmaxf(sc[j][0], sc[j][1]), fmaxf(sc[j][2], sc[j][3]));
            #pragma unroll
            for (int off = 16; off > 0; off >>= 1)
                mx = fmaxf(mx, __shfl_xor_sync(0xffffffffu, mx, off));
            const float oldM = sM[q];
            const float newM = fmaxf(oldM, mx);
            const float alpha = __expf(oldM - newM);
            float4 p;
            p.x = __expf(sc[j][0] - newM);
            p.y = __expf(sc[j][1] - newM);
            p.z = __expf(sc[j][2] - newM);
            p.w = __expf(sc[j][3] - newM);
            *reinterpret_cast<float4*>(&sP[q * TILE + 4 * lane]) = p;
            float rs = p.x + p.y + p.z + p.w;
            #pragma unroll
            for (int off = 16; off > 0; off >>= 1)
                rs += __shfl_xor_sync(0xffffffffu, rs, off);
            if (lane == 0) { sM[q] = newM; sL[q] = sL[q] * alpha + rs; sA[q] = alpha; }
        }
        __syncthreads();

        // ---- rescale + accumulate O: acc[j][i] over c = lane + 32*i ----
        #pragma unroll
        for (int j = 0; j < 3; ++j) {
            const float al = sA[q0 + j];
            #pragma unroll
            for (int i = 0; i < 3; ++i) acc[j][i] *= al;
        }

        #pragma unroll 2
        for (int n4 = 0; n4 < TILE; n4 += 4) {
            float4 xv[3], pv[3];
            #pragma unroll
            for (int i = 0; i < 3; ++i)
                xv[i] = *reinterpret_cast<const float4*>(
                    &sX[(lane + 32 * i) * XSTRIDE + n4]);
            #pragma unroll
            for (int j = 0; j < 3; ++j)
                pv[j] = *reinterpret_cast<const float4*>(&sP[(q0 + j) * TILE + n4]);
            #pragma unroll
            for (int j = 0; j < 3; ++j) {
                #pragma unroll
                for (int i = 0; i < 3; ++i) {
                    acc[j][i] = fmaf(pv[j].x, xv[i].x, acc[j][i]);
                    acc[j][i] = fmaf(pv[j].y, xv[i].y, acc[j][i]);
                    acc[j][i] = fmaf(pv[j].z, xv[i].z, acc[j][i]);
                    acc[j][i] = fmaf(pv[j].w, xv[i].w, acc[j][i]);
                }
            }
        }
    }
    __syncthreads();

    const int base = (b * SPLITS + s) * RQ;
    if (tid < RQ) { g_Mx[base + tid] = sM[tid]; g_Lx[base + tid] = sL[tid]; }
    #pragma unroll
    for (int j = 0; j < 3; ++j)
        #pragma unroll
        for (int i = 0; i < 3; ++i)
            g_Ox[(base + q0 + j) * CH + lane + 32 * i] = acc[j][i];
}

// ---------------------------------------------------------------------------
// Kernel 3: combine split partials + output projection + residual.
// grid BATCH, 192 threads (thread = output dim d).
// ---------------------------------------------------------------------------
__global__ __launch_bounds__(192) void combine_proj_kernel(
    const float* __restrict__ z, const float* __restrict__ Wo,
    const float* __restrict__ bo, float* __restrict__ out)
{
    __shared__ float sOf[RQ * CH];
    __shared__ float sW[RQ * 8];
    __shared__ float sLi[RQ];
    const int b = blockIdx.x, tid = threadIdx.x;

    if (tid < RQ) {
        const int q = tid;
        float Mg = -1e30f;
        for (int s = 0; s < SPLITS; ++s)
            Mg = fmaxf(Mg, g_Mx[(b * SPLITS + s) * RQ + q]);
        float L = 0.f;
        for (int s = 0; s < SPLITS; ++s) {
            const float w = __expf(g_Mx[(b * SPLITS + s) * RQ + q] - Mg);
            sW[q * 8 + s] = w;
            L += w * g_Lx[(b * SPLITS + s) * RQ + q];
        }
        sLi[q] = 1.f / L;
    }
    __syncthreads();

    for (int o = tid; o < RQ * CH; o += 192) {
        const int q = o / CH, c = o - q * CH;
        float a = 0.f;
        #pragma unroll
        for (int s = 0; s < SPLITS; ++s)
            a = fmaf(sW[q * 8 + s], g_Ox[((b * SPLITS + s) * RQ + q) * CH + c], a);
        sOf[o] = a * sLi[q];
    }
    __syncthreads();

    float accv[MTOK];
    #pragma unroll
    for (int m = 0; m < MTOK; ++m)
        accv[m] = z[(b * MTOK + m) * DMODEL + tid] + bo[tid];

    for (int h = 0; h < HEADS; ++h) {
        #pragma unroll 4
        for (int c = 0; c < CH; ++c) {
            const float w = Wo[(h * CH + c) * DMODEL + tid];
            #pragma unroll
            for (int m = 0; m < MTOK; ++m)
                accv[m] = fmaf(sOf[(h * MTOK + m) * CH + c], w, accv[m]);
        }
    }
    #pragma unroll
    for (int m = 0; m < MTOK; ++m)
        out[(b * MTOK + m) * DMODEL + tid] = accv[m];
}

// ---------------------------------------------------------------------------
extern "C" void kernel_launch(void* const* d_in, const int* in_sizes, int n_in,
                              void* d_out, int out_size)
{
    const float* x  = (const float*)d_in[0];
    const float* z  = (const float*)d_in[1];
    const float* Wq = (const float*)d_in[2];
    const float* bq = (const float*)d_in[3];
    const float* Wo = (const float*)d_in[4];
    const float* bo = (const float*)d_in[5];
    float* out = (float*)d_out;

    const int smem_bytes = (RQ * CH + CH * XSTRIDE + RQ * TILE + 3 * RQ) * (int)sizeof(float);
    cudaFuncSetAttribute(attn_partial_kernel,
                         cudaFuncAttributeMaxDynamicSharedMemorySize, smem_bytes);

    qproj_kernel<<<BATCH, 256>>>(z, Wq, bq);
    attn_partial_kernel<<<dim3(SPLITS, BATCH), 256, smem_bytes>>>(x);
    combine_proj_kernel<<<BATCH, DMODEL>>>(z, Wo, bo, out);
}

// round 2
// speedup vs baseline: 1.5302x; 1.5302x over previous
#include <cuda_runtime.h>
#include <cuda_bf16.h>
#include <math.h>
#include <stdint.h>

#define BATCH   64
#define CH      96
#define HW      12544
#define MTOK    6
#define HEADS   4
#define RQ      24
#define DMODEL  192
#define QDIM    384
#define SCALE_F 0.10206207261596575f  // 96^-0.5
#define SPLITS  14
#define CHUNK   896         // HW / SPLITS
#define TILE    128
#define TILES_PER 7         // CHUNK / TILE
#define XSTR    136         // bf16 elems per X row (128 + 8 pad) -> 272B, conflict-free
#define QSTR    104         // bf16 elems per Q row (96 + 8 pad)  -> 208B, conflict-free
#define PSTR    136

// scratch (device globals: no allocation allowed)
__device__ float g_Q [BATCH * RQ * CH];
__device__ float g_Mx[BATCH * SPLITS * RQ];
__device__ float g_Lx[BATCH * SPLITS * RQ];
__device__ float g_Ox[BATCH * SPLITS * RQ * CH];

// ---------------------------------------------------------------------------
// PTX helpers
// ---------------------------------------------------------------------------
__device__ __forceinline__ uint32_t smem_u32(const void* p) {
    return (uint32_t)__cvta_generic_to_shared(p);
}
__device__ __forceinline__ void ldm_x4(uint32_t& r0, uint32_t& r1, uint32_t& r2,
                                       uint32_t& r3, uint32_t addr) {
    asm volatile("ldmatrix.sync.aligned.m8n8.x4.shared.b16 {%0,%1,%2,%3}, [%4];"
                 : "=r"(r0), "=r"(r1), "=r"(r2), "=r"(r3) : "r"(addr));
}
__device__ __forceinline__ void ldm_x4_t(uint32_t& r0, uint32_t& r1, uint32_t& r2,
                                         uint32_t& r3, uint32_t addr) {
    asm volatile("ldmatrix.sync.aligned.m8n8.x4.trans.shared.b16 {%0,%1,%2,%3}, [%4];"
                 : "=r"(r0), "=r"(r1), "=r"(r2), "=r"(r3) : "r"(addr));
}
__device__ __forceinline__ void ldm_x2(uint32_t& r0, uint32_t& r1, uint32_t addr) {
    asm volatile("ldmatrix.sync.aligned.m8n8.x2.shared.b16 {%0,%1}, [%2];"
                 : "=r"(r0), "=r"(r1) : "r"(addr));
}
__device__ __forceinline__ void mma16816(float* c, const uint32_t* a,
                                         uint32_t b0, uint32_t b1) {
    asm volatile("mma.sync.aligned.m16n8k16.row.col.f32.bf16.bf16.f32 "
                 "{%0,%1,%2,%3}, {%4,%5,%6,%7}, {%8,%9}, {%0,%1,%2,%3};"
                 : "+f"(c[0]), "+f"(c[1]), "+f"(c[2]), "+f"(c[3])
                 : "r"(a[0]), "r"(a[1]), "r"(a[2]), "r"(a[3]), "r"(b0), "r"(b1));
}

// ---------------------------------------------------------------------------
// Kernel 1: Q projection (column-parallel). grid BATCH, 384 threads.
// thread = output column col = h*96+c; computes 6 rows (m) with coalesced Wq.
// ---------------------------------------------------------------------------
__global__ __launch_bounds__(QDIM) void qproj_kernel(
    const float* __restrict__ z, const float* __restrict__ Wq,
    const float* __restrict__ bq)
{
    __shared__ float sz[MTOK * DMODEL];
    const int b = blockIdx.x, col = threadIdx.x;
    for (int i = col; i < MTOK * DMODEL; i += QDIM)
        sz[i] = z[b * MTOK * DMODEL + i];
    __syncthreads();

    float acc[MTOK];
    const float bqv = bq[col];
    #pragma unroll
    for (int m = 0; m < MTOK; ++m) acc[m] = bqv;

    #pragma unroll 4
    for (int k = 0; k < DMODEL; ++k) {
        const float w = Wq[k * QDIM + col];
        #pragma unroll
        for (int m = 0; m < MTOK; ++m)
            acc[m] = fmaf(sz[m * DMODEL + k], w, acc[m]);
    }
    const int h = col / CH, c = col - h * CH;
    #pragma unroll
    for (int m = 0; m < MTOK; ++m)
        g_Q[(b * RQ + h * MTOK + m) * CH + c] = acc[m] * SCALE_F;
}

// ---------------------------------------------------------------------------
// Kernel 2: bf16 tensor-core flash attention partials.
// grid (SPLITS, BATCH), 256 threads = 8 warps.
// Scores: S[32pad x 128], warp w owns cols [16w,16w+16), 2 m-tiles x 2 n-tiles.
// PV:     O[32pad x 96],  warp w owns m-tile (w&1), c-cols [24*(w>>1), +24).
// ---------------------------------------------------------------------------
__global__ __launch_bounds__(256, 3) void attn_partial_kernel(const float* __restrict__ x)
{
    extern __shared__ char smem[];
    __nv_bfloat16* sQ = (__nv_bfloat16*)smem;                 // 32*104*2 = 6656
    __nv_bfloat16* sX = (__nv_bfloat16*)(smem + 6656);        // 96*136*2 = 26112
    __nv_bfloat16* sP = (__nv_bfloat16*)(smem + 6656 + 26112);// 32*136*2 = 8704
    float* sMax = (float*)(smem + 6656 + 26112 + 8704);       // 8*32 = 1024B
    float* sSum = sMax + 8 * 32;                              // 1024B

    const int b = blockIdx.y, s = blockIdx.x;
    const int tid = threadIdx.x, lane = tid & 31, warp = tid >> 5;
    const int g = lane >> 2, tig = lane & 3;

    const uint32_t uQ = smem_u32(sQ);
    const uint32_t uX = smem_u32(sX);
    const uint32_t uP = smem_u32(sP);

    // ---- stage Q (fp32 -> bf16), rows 24..31 zero ----
    for (int i = tid; i < 32 * CH; i += 256) {
        const int r = i / CH, c = i - r * CH;
        const float v = (r < RQ) ? g_Q[(b * RQ + r) * CH + c] : 0.f;
        sQ[r * QSTR + c] = __float2bfloat16(v);
    }

    float runM[4], runL[4];
    #pragma unroll
    for (int j = 0; j < 4; ++j) { runM[j] = -1e30f; runL[j] = 0.f; }

    float oacc[12];   // 3 c-tiles x {r,r cols2} fragments
    #pragma unroll
    for (int j = 0; j < 12; ++j) oacc[j] = 0.f;

    const int mt_o  = warp & 1;
    const int cbase = 24 * (warp >> 1);
    const float* xb = x + (size_t)b * CH * HW + (size_t)s * CHUNK;

    for (int t = 0; t < TILES_PER; ++t) {
        __syncthreads();   // previous tile fully consumed; sQ visible on t=0

        // ---- stage X tile [96][128] fp32 -> bf16 ----
        {
            const float* xt = xb + t * TILE;
            for (int i = tid; i < CH * (TILE / 4); i += 256) {
                const int c  = i >> 5;          // 32 float4 per row
                const int n4 = (i & 31) << 2;
                float4 v = *reinterpret_cast<const float4*>(xt + (size_t)c * HW + n4);
                __nv_bfloat162 lo = __floats2bfloat162_rn(v.x, v.y);
                __nv_bfloat162 hi = __floats2bfloat162_rn(v.z, v.w);
                uint2 pk; pk.x = *(uint32_t*)&lo; pk.y = *(uint32_t*)&hi;
                *reinterpret_cast<uint2*>(&sX[c * XSTR + n4]) = pk;
            }
        }
        __syncthreads();

        // ---- scores: S[mt][nt] over warp's 16 cols ----
        float sc[2][2][4];
        #pragma unroll
        for (int mt = 0; mt < 2; ++mt)
            #pragma unroll
            for (int nt = 0; nt < 2; ++nt)
                #pragma unroll
                for (int k = 0; k < 4; ++k) sc[mt][nt][k] = 0.f;

        #pragma unroll
        for (int i = 0; i < 6; ++i) {     // k = 96 / 16
            uint32_t a0[4], a1[4], bfr[4];
            // A (Q) m-tiles 0,1
            ldm_x4(a0[0], a0[1], a0[2], a0[3],
                   uQ + (( (lane & 15)      ) * QSTR + i * 16 + (lane >> 4) * 8) * 2);
            ldm_x4(a1[0], a1[1], a1[2], a1[3],
                   uQ + ((16 + (lane & 15)  ) * QSTR + i * 16 + (lane >> 4) * 8) * 2);
            // B (X, k-major rows=c) trans: matrices {(k0,n0),(k8,n0),(k0,n8),(k8,n8)}
            {
                const int grp = lane >> 3;
                const int row = i * 16 + (grp & 1) * 8 + (lane & 7);
                const int col = 16 * warp + (grp >> 1) * 8;
                ldm_x4_t(bfr[0], bfr[1], bfr[2], bfr[3], uX + (row * XSTR + col) * 2);
            }
            mma16816(sc[0][0], a0, bfr[0], bfr[1]);
            mma16816(sc[0][1], a0, bfr[2], bfr[3]);
            mma16816(sc[1][0], a1, bfr[0], bfr[1]);
            mma16816(sc[1][1], a1, bfr[2], bfr[3]);
        }

        // ---- partial row-max within warp (4 lanes per row) ----
        float mp[4];
        #pragma unroll
        for (int mt = 0; mt < 2; ++mt)
            #pragma unroll
            for (int hl = 0; hl < 2; ++hl) {
                float m = fmaxf(fmaxf(sc[mt][0][hl*2], sc[mt][0][hl*2+1]),
                                fmaxf(sc[mt][1][hl*2], sc[mt][1][hl*2+1]));
                m = fmaxf(m, __shfl_xor_sync(0xffffffffu, m, 1));
                m = fmaxf(m, __shfl_xor_sync(0xffffffffu, m, 2));
                mp[mt*2 + hl] = m;
            }
        if (tig == 0) {
            #pragma unroll
            for (int j = 0; j < 4; ++j) sMax[warp * 32 + g + 8*j] = mp[j];
        }
        __syncthreads();

        // ---- global row max, exp, per-warp row-sum, P->smem ----
        float newM[4], alpha[4];
        #pragma unroll
        for (int j = 0; j < 4; ++j) {
            float m = runM[j];
            #pragma unroll
            for (int w = 0; w < 8; ++w) m = fmaxf(m, sMax[w * 32 + g + 8*j]);
            newM[j] = m;
            alpha[j] = __expf(runM[j] - m);
            runM[j] = m;
        }
        float rs[4] = {0.f, 0.f, 0.f, 0.f};
        #pragma unroll
        for (int mt = 0; mt < 2; ++mt)
            #pragma unroll
            for (int nt = 0; nt < 2; ++nt)
                #pragma unroll
                for (int hl = 0; hl < 2; ++hl) {
                    const int j = mt*2 + hl;
                    float p0 = __expf(sc[mt][nt][hl*2]   - newM[j]);
                    float p1 = __expf(sc[mt][nt][hl*2+1] - newM[j]);
                    rs[j] += p0 + p1;
                    __nv_bfloat162 h2 = __floats2bfloat162_rn(p0, p1);
                    const int row = 16*mt + g + 8*hl;
                    const int col = 16*warp + 8*nt + 2*tig;
                    *reinterpret_cast<__nv_bfloat162*>(&sP[row * PSTR + col]) = h2;
                }
        #pragma unroll
        for (int j = 0; j < 4; ++j) {
            rs[j] += __shfl_xor_sync(0xffffffffu, rs[j], 1);
            rs[j] += __shfl_xor_sync(0xffffffffu, rs[j], 2);
        }
        if (tig == 0) {
            #pragma unroll
            for (int j = 0; j < 4; ++j) sSum[warp * 32 + g + 8*j] = rs[j];
        }
        __syncthreads();   // sSum + sP ready for all warps

        #pragma unroll
        for (int j = 0; j < 4; ++j) {
            float sm = 0.f;
            #pragma unroll
            for (int w = 0; w < 8; ++w) sm += sSum[w * 32 + g + 8*j];
            runL[j] = runL[j] * alpha[j] + sm;
        }

        // ---- rescale O, then PV ----
        {
            const float a0v = alpha[2*mt_o], a1v = alpha[2*mt_o + 1];
            #pragma unroll
            for (int j = 0; j < 3; ++j) {
                oacc[4*j+0] *= a0v; oacc[4*j+1] *= a0v;
                oacc[4*j+2] *= a1v; oacc[4*j+3] *= a1v;
            }
        }
        #pragma unroll
        for (int i = 0; i < 8; ++i) {   // k = 128 / 16 over spatial n
            uint32_t a[4], b01[4], b2[2];
            ldm_x4(a[0], a[1], a[2], a[3],
                   uP + ((16*mt_o + (lane & 15)) * PSTR + i * 16 + (lane >> 4) * 8) * 2);
            // B = X^T via NON-trans on X[c][n]: matrices {(k0,c0),(k8,c0),(k0,c8),(k8,c8)}
            {
                const int grp = lane >> 3;
                const int row = cbase + (grp >> 1) * 8 + (lane & 7);
                const int col = i * 16 + (grp & 1) * 8;
                ldm_x4(b01[0], b01[1], b01[2], b01[3], uX + (row * XSTR + col) * 2);
            }
            {
                const int row = cbase + 16 + (lane & 7);
                const int col = i * 16 + ((lane >> 3) & 1) * 8;
                ldm_x2(b2[0], b2[1], uX + (row * XSTR + col) * 2);
            }
            mma16816(oacc + 0, a, b01[0], b01[1]);
            mma16816(oacc + 4, a, b01[2], b01[3]);
            mma16816(oacc + 8, a, b2[0],  b2[1]);
        }
    }

    // ---- epilogue: write partials ----
    const int base = (b * SPLITS + s) * RQ;
    {
        const int r0 = 16*mt_o + g;          // always < 24
        #pragma unroll
        for (int j = 0; j < 3; ++j) {
            const int c0 = cbase + 8*j + 2*tig;
            g_Ox[(base + r0) * CH + c0]     = oacc[4*j+0];
            g_Ox[(base + r0) * CH + c0 + 1] = oacc[4*j+1];
        }
        if (mt_o == 0) {                     // r1 = g+8 < 24 only for m-tile 0
            const int r1 = g + 8;
            #pragma unroll
            for (int j = 0; j < 3; ++j) {
                const int c0 = cbase + 8*j + 2*tig;
                g_Ox[(base + r1) * CH + c0]     = oacc[4*j+2];
                g_Ox[(base + r1) * CH + c0 + 1] = oacc[4*j+3];
            }
        }
    }
    if (warp == 0 && tig == 0) {
        #pragma unroll
        for (int j = 0; j < 3; ++j) {
            const int r = g + 8*j;           // 0..23
            g_Mx[base + r] = runM[j];
            g_Lx[base + r] = runL[j];
        }
    }
}

// ---------------------------------------------------------------------------
// Kernel 3: combine split partials + output projection + residual.
// ---------------------------------------------------------------------------
__global__ __launch_bounds__(DMODEL) void combine_proj_kernel(
    const float* __restrict__ z, const float* __restrict__ Wo,
    const float* __restrict__ bo, float* __restrict__ out)
{
    __shared__ float sOf[RQ * CH];
    __shared__ float sW[RQ * 16];
    __shared__ float sLi[RQ];
    const int b = blockIdx.x, tid = threadIdx.x;

    if (tid < RQ) {
        const int q = tid;
        float Mg = -1e30f;
        for (int s = 0; s < SPLITS; ++s)
            Mg = fmaxf(Mg, g_Mx[(b * SPLITS + s) * RQ + q]);
        float L = 0.f;
        for (int s = 0; s < SPLITS; ++s) {
            const float w = __expf(g_Mx[(b * SPLITS + s) * RQ + q] - Mg);
            sW[q * 16 + s] = w;
            L += w * g_Lx[(b * SPLITS + s) * RQ + q];
        }
        sLi[q] = 1.f / L;
    }
    __syncthreads();

    for (int o = tid; o < RQ * CH; o += DMODEL) {
        const int q = o / CH, c = o - q * CH;
        float a = 0.f;
        #pragma unroll
        for (int s = 0; s < SPLITS; ++s)
            a = fmaf(sW[q * 16 + s], g_Ox[((b * SPLITS + s) * RQ + q) * CH + c], a);
        sOf[o] = a * sLi[q];
    }
    __syncthreads();

    float accv[MTOK];
    #pragma unroll
    for (int m = 0; m < MTOK; ++m)
        accv[m] = z[(b * MTOK + m) * DMODEL + tid] + bo[tid];

    for (int h = 0; h < HEADS; ++h) {
        #pragma unroll 4
        for (int c = 0; c < CH; ++c) {
            const float w = Wo[(h * CH + c) * DMODEL + tid];
            #pragma unroll
            for (int m = 0; m < MTOK; ++m)
                accv[m] = fmaf(sOf[(h * MTOK + m) * CH + c], w, accv[m]);
        }
    }
    #pragma unroll
    for (int m = 0; m < MTOK; ++m)
        out[(b * MTOK + m) * DMODEL + tid] = accv[m];
}

// ---------------------------------------------------------------------------
extern "C" void kernel_launch(void* const* d_in, const int* in_sizes, int n_in,
                              void* d_out, int out_size)
{
    const float* x  = (const float*)d_in[0];
    const float* z  = (const float*)d_in[1];
    const float* Wq = (const float*)d_in[2];
    const float* bq = (const float*)d_in[3];
    const float* Wo = (const float*)d_in[4];
    const float* bo = (const float*)d_in[5];
    float* out = (float*)d_out;

    const int smem_bytes = 6656 + 26112 + 8704 + 2048;   // 43520
    static int configured = 0;
    cudaFuncSetAttribute(attn_partial_kernel,
                         cudaFuncAttributeMaxDynamicSharedMemorySize, smem_bytes);
    (void)configured;

    qproj_kernel<<<BATCH, QDIM>>>(z, Wq, bq);
    attn_partial_kernel<<<dim3(SPLITS, BATCH), 256, smem_bytes>>>(x);
    combine_proj_kernel<<<BATCH, DMODEL>>>(z, Wo, bo, out);
}

// round 4
// speedup vs baseline: 2.1305x; 1.3922x over previous
#include <cuda_runtime.h>
#include <cuda_bf16.h>
#include <math.h>
#include <stdint.h>

#define BATCH   64
#define CH      96
#define HW      12544
#define MTOK    6
#define HEADS   4
#define RQ      24
#define DMODEL  192
#define QDIM    384
#define SCALE_F 0.10206207261596575f  // 96^-0.5
#define SPLITS  14
#define CHUNK   896         // HW / SPLITS
#define TILE    128
#define TILES_PER 7         // CHUNK / TILE
#define XSTR    136         // bf16 elems per X row (128 + 8 pad)
#define FSTR    132         // fp32 elems per staging row (128 + 4 pad)
#define QSTR    104         // bf16 elems per Q row (96 + 8 pad)
#define PSTR    136

// scratch (device globals: no allocation allowed)
__device__ float g_Qa[BATCH * RQ * CH];
__device__ float g_Qb[BATCH * RQ * CH];
__device__ float g_Mx[BATCH * SPLITS * RQ];
__device__ float g_Lx[BATCH * SPLITS * RQ];
__device__ float g_Ox[BATCH * SPLITS * RQ * CH];

// ---------------------------------------------------------------------------
// PTX helpers
// ---------------------------------------------------------------------------
__device__ __forceinline__ uint32_t smem_u32(const void* p) {
    return (uint32_t)__cvta_generic_to_shared(p);
}
__device__ __forceinline__ void ldm_x4(uint32_t& r0, uint32_t& r1, uint32_t& r2,
                                       uint32_t& r3, uint32_t addr) {
    asm volatile("ldmatrix.sync.aligned.m8n8.x4.shared.b16 {%0,%1,%2,%3}, [%4];"
                 : "=r"(r0), "=r"(r1), "=r"(r2), "=r"(r3) : "r"(addr));
}
__device__ __forceinline__ void ldm_x4_t(uint32_t& r0, uint32_t& r1, uint32_t& r2,
                                         uint32_t& r3, uint32_t addr) {
    asm volatile("ldmatrix.sync.aligned.m8n8.x4.trans.shared.b16 {%0,%1,%2,%3}, [%4];"
                 : "=r"(r0), "=r"(r1), "=r"(r2), "=r"(r3) : "r"(addr));
}
__device__ __forceinline__ void ldm_x2(uint32_t& r0, uint32_t& r1, uint32_t addr) {
    asm volatile("ldmatrix.sync.aligned.m8n8.x2.shared.b16 {%0,%1}, [%2];"
                 : "=r"(r0), "=r"(r1) : "r"(addr));
}
__device__ __forceinline__ void mma16816(float* c, const uint32_t* a,
                                         uint32_t b0, uint32_t b1) {
    asm volatile("mma.sync.aligned.m16n8k16.row.col.f32.bf16.bf16.f32 "
                 "{%0,%1,%2,%3}, {%4,%5,%6,%7}, {%8,%9}, {%0,%1,%2,%3};"
                 : "+f"(c[0]), "+f"(c[1]), "+f"(c[2]), "+f"(c[3])
                 : "r"(a[0]), "r"(a[1]), "r"(a[2]), "r"(a[3]), "r"(b0), "r"(b1));
}
__device__ __forceinline__ void cpasync16(uint32_t dst, const void* src) {
    asm volatile("cp.async.cg.shared.global [%0], [%1], 16;" :: "r"(dst), "l"(src));
}
#define CP_COMMIT() asm volatile("cp.async.commit_group;" ::: "memory")
#define CP_WAIT0()  asm volatile("cp.async.wait_group 0;" ::: "memory")

// ---------------------------------------------------------------------------
// Kernel 1: Q projection, split-k x2. grid (BATCH, 2), 384 threads.
// CTA (b, h2) handles k in [96*h2, 96*h2+96); partials summed by attn staging.
// ---------------------------------------------------------------------------
__global__ __launch_bounds__(QDIM) void qproj_kernel(
    const float* __restrict__ z, const float* __restrict__ Wq,
    const float* __restrict__ bq)
{
    __shared__ float sz[MTOK * 96];
    const int b = blockIdx.x, h2 = blockIdx.y, col = threadIdx.x;
    for (int i = col; i < MTOK * 96; i += QDIM) {
        const int m = i / 96, k = i - m * 96;
        sz[i] = z[b * MTOK * DMODEL + m * DMODEL + h2 * 96 + k];
    }
    __syncthreads();

    float acc[MTOK];
    const float b0 = (h2 == 0) ? bq[col] : 0.f;
    #pragma unroll
    for (int m = 0; m < MTOK; ++m) acc[m] = b0;

    const float* Wqp = Wq + (size_t)(h2 * 96) * QDIM + col;
    #pragma unroll 16
    for (int k = 0; k < 96; ++k) {
        const float w = Wqp[k * QDIM];
        #pragma unroll
        for (int m = 0; m < MTOK; ++m)
            acc[m] = fmaf(sz[m * 96 + k], w, acc[m]);
    }
    const int h = col / CH, c = col - h * CH;
    float* dst = (h2 == 0) ? g_Qa : g_Qb;
    #pragma unroll
    for (int m = 0; m < MTOK; ++m)
        dst[(b * RQ + h * MTOK + m) * CH + c] = acc[m] * SCALE_F;
}

// ---------------------------------------------------------------------------
// Kernel 2: bf16 tensor-core flash attention partials, cp.async pipelined.
// grid (SPLITS, BATCH), 256 threads = 8 warps, 2 CTAs/SM.
// ---------------------------------------------------------------------------
__global__ __launch_bounds__(256, 2) void attn_partial_kernel(const float* __restrict__ x)
{
    extern __shared__ char smem[];
    // fp32 staging: 96*132*4 = 50688
    float*         sXf = (float*)smem;
    __nv_bfloat16* sQ  = (__nv_bfloat16*)(smem + 50688);            // 32*104*2 = 6656
    __nv_bfloat16* sX  = (__nv_bfloat16*)(smem + 50688 + 6656);     // 96*136*2 = 26112
    __nv_bfloat16* sP  = (__nv_bfloat16*)(smem + 50688 + 6656 + 26112); // 32*136*2 = 8704
    float* sMax = (float*)(smem + 50688 + 6656 + 26112 + 8704);     // 1024
    float* sSum = sMax + 8 * 32;                                    // 1024

    const int b = blockIdx.y, s = blockIdx.x;
    const int tid = threadIdx.x, lane = tid & 31, warp = tid >> 5;
    const int g = lane >> 2, tig = lane & 3;

    const uint32_t uQ  = smem_u32(sQ);
    const uint32_t uX  = smem_u32(sX);
    const uint32_t uP  = smem_u32(sP);
    const uint32_t uXf = smem_u32(sXf);

    const float* xb = x + (size_t)b * CH * HW + (size_t)s * CHUNK;

    // ---- issue cp.async for tile 0 ----
    {
        const float* xt = xb;
        #pragma unroll
        for (int i = tid; i < CH * (TILE / 4); i += 256) {
            const int c = i >> 5, n4 = (i & 31) << 2;
            cpasync16(uXf + (c * FSTR + n4) * 4, xt + (size_t)c * HW + n4);
        }
        CP_COMMIT();
    }

    // ---- stage Q (sum of split-k halves, fp32 -> bf16), rows 24..31 zero ----
    for (int i = tid; i < 32 * CH; i += 256) {
        const int r = i / CH, c = i - r * CH;
        const int idx = (b * RQ + r) * CH + c;
        const float v = (r < RQ) ? (g_Qa[idx] + g_Qb[idx]) : 0.f;
        sQ[r * QSTR + c] = __float2bfloat16(v);
    }
    __syncthreads();

    // ---- hoist Q fragments (loop-invariant): 12 x ldm_x4 = 48 regs ----
    uint32_t qf[2][6][4];
    #pragma unroll
    for (int i = 0; i < 6; ++i) {
        ldm_x4(qf[0][i][0], qf[0][i][1], qf[0][i][2], qf[0][i][3],
               uQ + (((lane & 15)     ) * QSTR + i * 16 + (lane >> 4) * 8) * 2);
        ldm_x4(qf[1][i][0], qf[1][i][1], qf[1][i][2], qf[1][i][3],
               uQ + ((16 + (lane & 15)) * QSTR + i * 16 + (lane >> 4) * 8) * 2);
    }

    float runM[4], runL[4];
    #pragma unroll
    for (int j = 0; j < 4; ++j) { runM[j] = -1e30f; runL[j] = 0.f; }
    float oacc[12];
    #pragma unroll
    for (int j = 0; j < 12; ++j) oacc[j] = 0.f;

    const int mt_o  = warp & 1;
    const int cbase = 24 * (warp >> 1);

    for (int t = 0; t < TILES_PER; ++t) {
        CP_WAIT0();
        __syncthreads();   // staging tile t landed; prior tile fully consumed

        // ---- convert staging fp32 -> bf16 sX ----
        #pragma unroll
        for (int i = tid; i < CH * (TILE / 4); i += 256) {
            const int c = i >> 5, n4 = (i & 31) << 2;
            float4 v = *reinterpret_cast<const float4*>(&sXf[c * FSTR + n4]);
            __nv_bfloat162 lo = __floats2bfloat162_rn(v.x, v.y);
            __nv_bfloat162 hi = __floats2bfloat162_rn(v.z, v.w);
            uint2 pk; pk.x = *(uint32_t*)&lo; pk.y = *(uint32_t*)&hi;
            *reinterpret_cast<uint2*>(&sX[c * XSTR + n4]) = pk;
        }
        __syncthreads();   // sX ready; sXf free for next prefetch

        // ---- prefetch tile t+1 into staging (overlaps all compute below) ----
        if (t + 1 < TILES_PER) {
            const float* xt = xb + (t + 1) * TILE;
            #pragma unroll
            for (int i = tid; i < CH * (TILE / 4); i += 256) {
                const int c = i >> 5, n4 = (i & 31) << 2;
                cpasync16(uXf + (c * FSTR + n4) * 4, xt + (size_t)c * HW + n4);
            }
        }
        CP_COMMIT();

        // ---- scores ----
        float sc[2][2][4];
        #pragma unroll
        for (int mt = 0; mt < 2; ++mt)
            #pragma unroll
            for (int nt = 0; nt < 2; ++nt)
                #pragma unroll
                for (int k = 0; k < 4; ++k) sc[mt][nt][k] = 0.f;

        #pragma unroll
        for (int i = 0; i < 6; ++i) {
            uint32_t bfr[4];
            const int grp = lane >> 3;
            const int row = i * 16 + (grp & 1) * 8 + (lane & 7);
            const int col = 16 * warp + (grp >> 1) * 8;
            ldm_x4_t(bfr[0], bfr[1], bfr[2], bfr[3], uX + (row * XSTR + col) * 2);
            mma16816(sc[0][0], qf[0][i], bfr[0], bfr[1]);
            mma16816(sc[0][1], qf[0][i], bfr[2], bfr[3]);
            mma16816(sc[1][0], qf[1][i], bfr[0], bfr[1]);
            mma16816(sc[1][1], qf[1][i], bfr[2], bfr[3]);
        }

        // ---- partial row-max within warp ----
        float mp[4];
        #pragma unroll
        for (int mt = 0; mt < 2; ++mt)
            #pragma unroll
            for (int hl = 0; hl < 2; ++hl) {
                float m = fmaxf(fmaxf(sc[mt][0][hl*2], sc[mt][0][hl*2+1]),
                                fmaxf(sc[mt][1][hl*2], sc[mt][1][hl*2+1]));
                m = fmaxf(m, __shfl_xor_sync(0xffffffffu, m, 1));
                m = fmaxf(m, __shfl_xor_sync(0xffffffffu, m, 2));
                mp[mt*2 + hl] = m;
            }
        if (tig == 0) {
            #pragma unroll
            for (int j = 0; j < 4; ++j) sMax[warp * 32 + g + 8*j] = mp[j];
        }
        __syncthreads();

        // ---- global row max, exp, per-warp row-sum, P->smem ----
        float newM[4], alpha[4];
        #pragma unroll
        for (int j = 0; j < 4; ++j) {
            float m = runM[j];
            #pragma unroll
            for (int w = 0; w < 8; ++w) m = fmaxf(m, sMax[w * 32 + g + 8*j]);
            newM[j] = m;
            alpha[j] = __expf(runM[j] - m);
            runM[j] = m;
        }
        float rs[4] = {0.f, 0.f, 0.f, 0.f};
        #pragma unroll
        for (int mt = 0; mt < 2; ++mt)
            #pragma unroll
            for (int nt = 0; nt < 2; ++nt)
                #pragma unroll
                for (int hl = 0; hl < 2; ++hl) {
                    const int j = mt*2 + hl;
                    float p0 = __expf(sc[mt][nt][hl*2]   - newM[j]);
                    float p1 = __expf(sc[mt][nt][hl*2+1] - newM[j]);
                    rs[j] += p0 + p1;
                    __nv_bfloat162 h2 = __floats2bfloat162_rn(p0, p1);
                    const int row = 16*mt + g + 8*hl;
                    const int col = 16*warp + 8*nt + 2*tig;
                    *reinterpret_cast<__nv_bfloat162*>(&sP[row * PSTR + col]) = h2;
                }
        #pragma unroll
        for (int j = 0; j < 4; ++j) {
            rs[j] += __shfl_xor_sync(0xffffffffu, rs[j], 1);
            rs[j] += __shfl_xor_sync(0xffffffffu, rs[j], 2);
        }
        if (tig == 0) {
            #pragma unroll
            for (int j = 0; j < 4; ++j) sSum[warp * 32 + g + 8*j] = rs[j];
        }
        __syncthreads();   // sSum + sP ready

        #pragma unroll
        for (int j = 0; j < 4; ++j) {
            float sm = 0.f;
            #pragma unroll
            for (int w = 0; w < 8; ++w) sm += sSum[w * 32 + g + 8*j];
            runL[j] = runL[j] * alpha[j] + sm;
        }

        // ---- rescale O, then PV ----
        {
            const float a0v = alpha[2*mt_o], a1v = alpha[2*mt_o + 1];
            #pragma unroll
            for (int j = 0; j < 3; ++j) {
                oacc[4*j+0] *= a0v; oacc[4*j+1] *= a0v;
                oacc[4*j+2] *= a1v; oacc[4*j+3] *= a1v;
            }
        }
        #pragma unroll
        for (int i = 0; i < 8; ++i) {
            uint32_t a[4], b01[4], b2[2];
            ldm_x4(a[0], a[1], a[2], a[3],
                   uP + ((16*mt_o + (lane & 15)) * PSTR + i * 16 + (lane >> 4) * 8) * 2);
            {
                const int grp = lane >> 3;
                const int row = cbase + (grp >> 1) * 8 + (lane & 7);
                const int col = i * 16 + (grp & 1) * 8;
                ldm_x4(b01[0], b01[1], b01[2], b01[3], uX + (row * XSTR + col) * 2);
            }
            {
                const int row = cbase + 16 + (lane & 7);
                const int col = i * 16 + ((lane >> 3) & 1) * 8;
                ldm_x2(b2[0], b2[1], uX + (row * XSTR + col) * 2);
            }
            mma16816(oacc + 0, a, b01[0], b01[1]);
            mma16816(oacc + 4, a, b01[2], b01[3]);
            mma16816(oacc + 8, a, b2[0],  b2[1]);
        }
    }

    // ---- epilogue: write partials ----
    const int base = (b * SPLITS + s) * RQ;
    {
        const int r0 = 16*mt_o + g;
        #pragma unroll
        for (int j = 0; j < 3; ++j) {
            const int c0 = cbase + 8*j + 2*tig;
            g_Ox[(base + r0) * CH + c0]     = oacc[4*j+0];
            g_Ox[(base + r0) * CH + c0 + 1] = oacc[4*j+1];
        }
        if (mt_o == 0) {
            const int r1 = g + 8;
            #pragma unroll
            for (int j = 0; j < 3; ++j) {
                const int c0 = cbase + 8*j + 2*tig;
                g_Ox[(base + r1) * CH + c0]     = oacc[4*j+2];
                g_Ox[(base + r1) * CH + c0 + 1] = oacc[4*j+3];
            }
        }
    }
    if (warp == 0 && tig == 0) {
        #pragma unroll
        for (int j = 0; j < 3; ++j) {
            const int r = g + 8*j;
            g_Mx[base + r] = runM[j];
            g_Lx[base + r] = runL[j];
        }
    }
}

// ---------------------------------------------------------------------------
// Kernel 3: combine split partials + output projection + residual.
// ---------------------------------------------------------------------------
__global__ __launch_bounds__(DMODEL) void combine_proj_kernel(
    const float* __restrict__ z, const float* __restrict__ Wo,
    const float* __restrict__ bo, float* __restrict__ out)
{
    __shared__ float sOf[RQ * CH];
    __shared__ float sW[RQ * 16];
    __shared__ float sLi[RQ];
    const int b = blockIdx.x, tid = threadIdx.x;

    if (tid < RQ) {
        const int q = tid;
        float Mg = -1e30f;
        for (int s = 0; s < SPLITS; ++s)
            Mg = fmaxf(Mg, g_Mx[(b * SPLITS + s) * RQ + q]);
        float L = 0.f;
        for (int s = 0; s < SPLITS; ++s) {
            const float w = __expf(g_Mx[(b * SPLITS + s) * RQ + q] - Mg);
            sW[q * 16 + s] = w;
            L += w * g_Lx[(b * SPLITS + s) * RQ + q];
        }
        sLi[q] = 1.f / L;
    }
    __syncthreads();

    for (int o = tid; o < RQ * CH; o += DMODEL) {
        const int q = o / CH, c = o - q * CH;
        float a = 0.f;
        #pragma unroll
        for (int s = 0; s < SPLITS; ++s)
            a = fmaf(sW[q * 16 + s], g_Ox[((b * SPLITS + s) * RQ + q) * CH + c], a);
        sOf[o] = a * sLi[q];
    }
    __syncthreads();

    float accv[MTOK];
    #pragma unroll
    for (int m = 0; m < MTOK; ++m)
        accv[m] = z[(b * MTOK + m) * DMODEL + tid] + bo[tid];

    for (int h = 0; h < HEADS; ++h) {
        #pragma unroll 4
        for (int c = 0; c < CH; ++c) {
            const float w = Wo[(h * CH + c) * DMODEL + tid];
            #pragma unroll
            for (int m = 0; m < MTOK; ++m)
                accv[m] = fmaf(sOf[(h * MTOK + m) * CH + c], w, accv[m]);
        }
    }
    #pragma unroll
    for (int m = 0; m < MTOK; ++m)
        out[(b * MTOK + m) * DMODEL + tid] = accv[m];
}

// ---------------------------------------------------------------------------
extern "C" void kernel_launch(void* const* d_in, const int* in_sizes, int n_in,
                              void* d_out, int out_size)
{
    const float* x  = (const float*)d_in[0];
    const float* z  = (const float*)d_in[1];
    const float* Wq = (const float*)d_in[2];
    const float* bq = (const float*)d_in[3];
    const float* Wo = (const float*)d_in[4];
    const float* bo = (const float*)d_in[5];
    float* out = (float*)d_out;

    const int smem_bytes = 50688 + 6656 + 26112 + 8704 + 2048;   // 94208
    cudaFuncSetAttribute(attn_partial_kernel,
                         cudaFuncAttributeMaxDynamicSharedMemorySize, smem_bytes);

    qproj_kernel<<<dim3(BATCH, 2), QDIM>>>(z, Wq, bq);
    attn_partial_kernel<<<dim3(SPLITS, BATCH), 256, smem_bytes>>>(x);
    combine_proj_kernel<<<BATCH, DMODEL>>>(z, Wo, bo, out);
}